// round 5
// baseline (speedup 1.0000x reference)
#include <cuda_runtime.h>

#define N_ROWS   131072
#define KCODES   1024
#define DIMV     64
#define RPB      128                  // rows per block
#define CPT      64                   // codes per smem tile
#define NTILES   (KCODES / CPT)       // 16
#define NBLOCKS  (N_ROWS / RPB)       // 1024
#define THREADS  256
#define EPS_GAP  5e-3f
#define AMB_CAP  131072

__device__ float g_e2[KCODES];
__device__ float g_part[NBLOCKS];
__device__ int   g_idx[N_ROWS];
__device__ int   g_amb[AMB_CAP];
__device__ int   g_namb;

// Packed fp32x2 helpers (Blackwell FFMA2 path, PTX-only)
#define FMA2(acc, a, b)  asm("fma.rn.f32x2 %0, %1, %2, %0;" : "+l"(acc) : "l"(a), "l"(b))
#define PACK2(out, x)    asm("mov.b64 %0, {%1, %1};" : "=l"(out) : "f"(x))
#define UNPACK2(lo, hi, v) asm("mov.b64 {%0, %1}, %2;" : "=f"(lo), "=f"(hi) : "l"(v))

// ||e_k||^2 per code (scoring only; exactness non-binding) + reset ambig counter
__global__ void e2_kernel(const float* __restrict__ emb) {
    if (blockIdx.x == 0 && threadIdx.x == 0) g_namb = 0;
    int k = blockIdx.x * 256 + threadIdx.x;
    if (k < KCODES) {
        const float* row = emb + k * DIMV;
        float s = 0.f;
#pragma unroll
        for (int i = 0; i < DIMV; i++) {
            float v = row[i];
            s = __fadd_rn(s, __fmul_rn(v, v));
        }
        g_e2[k] = s;
    }
}

__global__ __launch_bounds__(THREADS) void vq_kernel(
    const float* __restrict__ z, const float* __restrict__ emb)
{
    __shared__ float zs[DIMV * RPB];   // 32KB, [d][r]
    __shared__ float cs[DIMV * CPT];   // 16KB, transposed + swizzled code tile
    __shared__ float As[RPB];

    const int tid = threadIdx.x;
    const int tx = tid & 15;           // code group (4 codes)
    const int ty = tid >> 4;           // row group (8 rows)

    const int n0 = blockIdx.x * RPB;
    const int b  = n0 >> 12;
    const int hw = n0 & 4095;
    const int zbase = b * 262144 + hw;

    // load z tile [64 d][128 r], coalesced float4
#pragma unroll
    for (int i = 0; i < 8; ++i) {
        int idx4 = i * THREADS + tid;
        int d  = idx4 >> 5;
        int r4 = (idx4 & 31) << 2;
        float4 v = *(const float4*)(z + zbase + d * 4096 + r4);
        *(float4*)&zs[d * 128 + r4] = v;
    }
    __syncthreads();

    if (tid < RPB) {
        float a = 0.f;
#pragma unroll
        for (int d = 0; d < DIMV; ++d) {
            float v = zs[d * 128 + tid];
            a = __fadd_rn(a, __fmul_rn(v, v));
        }
        As[tid] = a;
    }
    __syncthreads();

    float best_v[8], sec_v[8];
    int   best_k[8];
#pragma unroll
    for (int r = 0; r < 8; ++r) {
        best_v[r] = 3.4028235e38f; sec_v[r] = 3.4028235e38f; best_k[r] = 0;
    }

    for (int t = 0; t < NTILES; ++t) {
        const float* eb = emb + t * CPT * DIMV;
#pragma unroll
        for (int i = 0; i < (CPT * DIMV) / THREADS; ++i) {   // 16
            int idx = i * THREADS + tid;
            int k = idx >> 6, d = idx & 63;
            int gg = (k >> 2) ^ (d & 15);
            cs[d * 64 + gg * 4 + (k & 3)] = eb[idx];
        }
        __syncthreads();

        unsigned long long acc[4][4];
#pragma unroll
        for (int p = 0; p < 4; ++p)
#pragma unroll
            for (int j = 0; j < 4; ++j) acc[p][j] = 0ull;

#pragma unroll 4
        for (int d = 0; d < DIMV; ++d) {
            const float* zr = &zs[d * 128 + ty * 8];
            unsigned long long z0 = *(const unsigned long long*)(zr + 0);
            unsigned long long z1 = *(const unsigned long long*)(zr + 2);
            unsigned long long z2 = *(const unsigned long long*)(zr + 4);
            unsigned long long z3 = *(const unsigned long long*)(zr + 6);
            int gg = tx ^ (d & 15);
            float4 c4 = *(const float4*)&cs[d * 64 + gg * 4];
            unsigned long long c0, c1, c2, c3;
            PACK2(c0, c4.x); PACK2(c1, c4.y); PACK2(c2, c4.z); PACK2(c3, c4.w);
            FMA2(acc[0][0], z0, c0); FMA2(acc[1][0], z1, c0);
            FMA2(acc[2][0], z2, c0); FMA2(acc[3][0], z3, c0);
            FMA2(acc[0][1], z0, c1); FMA2(acc[1][1], z1, c1);
            FMA2(acc[2][1], z2, c1); FMA2(acc[3][1], z3, c1);
            FMA2(acc[0][2], z0, c2); FMA2(acc[1][2], z1, c2);
            FMA2(acc[2][2], z2, c2); FMA2(acc[3][2], z3, c2);
            FMA2(acc[0][3], z0, c3); FMA2(acc[1][3], z1, c3);
            FMA2(acc[2][3], z2, c3); FMA2(acc[3][3], z3, c3);
        }

        // score = (||z||^2 - 2*dot) + ||e||^2 ; strict '<' over ascending k
        const int kbase = t * CPT + tx * 4;
#pragma unroll
        for (int j = 0; j < 4; ++j) {
            float e2v = g_e2[kbase + j];
#pragma unroll
            for (int p = 0; p < 4; ++p) {
                float lo, hi;
                UNPACK2(lo, hi, acc[p][j]);
                int r0 = ty * 8 + p * 2;
                float slo = __fadd_rn(__fsub_rn(As[r0],     __fmul_rn(2.f, lo)), e2v);
                float shi = __fadd_rn(__fsub_rn(As[r0 + 1], __fmul_rn(2.f, hi)), e2v);
                int r = p * 2;
                if (slo < best_v[r]) { sec_v[r] = best_v[r]; best_v[r] = slo; best_k[r] = kbase + j; }
                else if (slo < sec_v[r]) sec_v[r] = slo;
                if (shi < best_v[r+1]) { sec_v[r+1] = best_v[r+1]; best_v[r+1] = shi; best_k[r+1] = kbase + j; }
                else if (shi < sec_v[r+1]) sec_v[r+1] = shi;
            }
        }
        __syncthreads();
    }

    // per-row (best, idx, second) reduction across 16 threads; overlay on zs
    float* rv = zs;                    // 2048
    int*   ri = (int*)(zs + 2048);     // 2048
    float* rs = zs + 4096;             // 2048
#pragma unroll
    for (int p = 0; p < 8; ++p) {
        int r = ty * 8 + p;
        rv[r * 16 + tx] = best_v[p];
        ri[r * 16 + tx] = best_k[p];
        rs[r * 16 + tx] = sec_v[p];
    }
    __syncthreads();
    if (tid < RPB) {
        float bv = rv[tid * 16];
        int   bk = ri[tid * 16];
        int   bj = 0;
#pragma unroll
        for (int j = 1; j < 16; ++j) {
            float v = rv[tid * 16 + j];
            int  kk = ri[tid * 16 + j];
            if (v < bv || (v == bv && kk < bk)) { bv = v; bk = kk; bj = j; }
        }
        float sv = rs[tid * 16 + bj];
#pragma unroll
        for (int j = 0; j < 16; ++j)
            if (j != bj) sv = fminf(sv, rv[tid * 16 + j]);
        int n = n0 + tid;
        g_idx[n] = bk;
        if (sv - bv < EPS_GAP) {
            int slot = atomicAdd(&g_namb, 1);
            if (slot < AMB_CAP) g_amb[slot] = n;
        }
    }
}

// exact (fp64) re-argmin for near-tie rows; one block per row
__global__ __launch_bounds__(256) void fixup_kernel(
    const float* __restrict__ z, const float* __restrict__ emb)
{
    __shared__ double zrow[DIMV];
    __shared__ double bvs[256];
    __shared__ int    bks[256];
    int namb = g_namb;
    if (namb > AMB_CAP) namb = AMB_CAP;
    for (int i = blockIdx.x; i < namb; i += gridDim.x) {
        int n = g_amb[i];
        int b  = n >> 12;
        int hw = n & 4095;
        const float* zp = z + b * 262144 + hw;
        if (threadIdx.x < DIMV) zrow[threadIdx.x] = (double)zp[threadIdx.x * 4096];
        __syncthreads();
        double bv = 1e300; int bk = 0;
        for (int k = threadIdx.x; k < KCODES; k += 256) {
            const float* e = emb + k * DIMV;
            double s = 0.0;
#pragma unroll
            for (int d = 0; d < DIMV; ++d) {
                double diff = zrow[d] - (double)e[d];
                s = fma(diff, diff, s);
            }
            if (s < bv) { bv = s; bk = k; }   // ascending k -> first occurrence
        }
        bvs[threadIdx.x] = bv; bks[threadIdx.x] = bk;
        __syncthreads();
        for (int o = 128; o > 0; o >>= 1) {
            if (threadIdx.x < o) {
                double ov = bvs[threadIdx.x + o]; int ok = bks[threadIdx.x + o];
                if (ov < bvs[threadIdx.x] ||
                    (ov == bvs[threadIdx.x] && ok < bks[threadIdx.x])) {
                    bvs[threadIdx.x] = ov; bks[threadIdx.x] = ok;
                }
            }
            __syncthreads();
        }
        if (threadIdx.x == 0) g_idx[n] = bks[0];
        __syncthreads();
    }
}

// gather codes per final index, write out, deterministic per-block loss partials
__global__ __launch_bounds__(THREADS) void out_loss_kernel(
    const float* __restrict__ z, const float* __restrict__ emb,
    float* __restrict__ out)
{
    __shared__ int   ks[RPB];
    __shared__ float wsum[8];
    const int tid = threadIdx.x;
    const int n0 = blockIdx.x * RPB;
    const int b  = n0 >> 12;
    const int hw = n0 & 4095;
    const int zbase = b * 262144 + hw;

    if (tid < RPB) ks[tid] = g_idx[n0 + tid];
    __syncthreads();

    float lsum = 0.f;
#pragma unroll
    for (int i = 0; i < (RPB * DIMV) / THREADS; ++i) {   // 32
        int idx = i * THREADS + tid;
        int d = idx >> 7, r = idx & 127;
        int kk = ks[r];
        float q = __ldg(&emb[kk * DIMV + d]);
        int g = zbase + d * 4096 + r;
        out[g] = q;
        float diff = q - __ldg(&z[g]);
        lsum = fmaf(diff, diff, lsum);
    }
#pragma unroll
    for (int o = 16; o > 0; o >>= 1)
        lsum += __shfl_down_sync(0xffffffffu, lsum, o);
    if ((tid & 31) == 0) wsum[tid >> 5] = lsum;
    __syncthreads();
    if (tid == 0) {
        float s = 0.f;
#pragma unroll
        for (int w = 0; w < 8; ++w) s += wsum[w];
        g_part[blockIdx.x] = s;
    }
}

__global__ void loss_kernel(float* __restrict__ out, int loss_off) {
    __shared__ float s[256];
    int t = threadIdx.x;
    float v = g_part[t] + g_part[t + 256] + g_part[t + 512] + g_part[t + 768];
    s[t] = v;
    __syncthreads();
    for (int o = 128; o > 0; o >>= 1) {
        if (t < o) s[t] += s[t + o];
        __syncthreads();
    }
    if (t == 0) {
        float m = s[0] * (1.0f / 8388608.0f);
        out[loss_off] = fmaf(0.25f, m, m);     // codebook + 0.25*commit
    }
}

extern "C" void kernel_launch(void* const* d_in, const int* in_sizes, int n_in,
                              void* d_out, int out_size) {
    const float* z   = (const float*)d_in[0];
    const float* emb = (const float*)d_in[1];
    float* out = (float*)d_out;
    e2_kernel<<<4, 256>>>(emb);
    vq_kernel<<<NBLOCKS, THREADS>>>(z, emb);
    fixup_kernel<<<512, 256>>>(z, emb);
    out_loss_kernel<<<NBLOCKS, THREADS>>>(z, emb, out);
    loss_kernel<<<1, 256>>>(out, out_size - 1);
}

// round 8
// speedup vs baseline: 1.0006x; 1.0006x over previous
#include <cuda_runtime.h>
#include <cuda_bf16.h>
#include <cstdint>

#define N_ROWS   131072
#define KCODES   1024
#define DIMV     64
#define RPB      256                 // rows per vq CTA
#define NBLOCKS  (N_ROWS / RPB)      // 512
#define THREADS  256
#define EPS_GAP  1.5e-2f
#define AMB_CAP  131072

// vq smem: zstage fp32 [64][260] = 66560B (overlaid later by B chunk bufs),
// C[1024] fp32 at 66560. B bufs: buf0 hi@0 lo@16384, buf1 hi@32768 lo@49152.
#define ZS_STRIDE 260
#define C_OFF     66560
#define SMEM_VQ   (66560 + 4096)

__device__ float          g_e2[KCODES];
__device__ __nv_bfloat16  g_ehi[KCODES * DIMV];
__device__ __nv_bfloat16  g_elo[KCODES * DIMV];
__device__ float          g_part[1024];
__device__ int            g_idx[N_ROWS];
__device__ int            g_amb[AMB_CAP];
__device__ int            g_namb;

// ---------------- helpers ----------------
__device__ __forceinline__ void mma_bf16(float* d, uint32_t a0, uint32_t a1,
                                         uint32_t a2, uint32_t a3,
                                         uint32_t b0, uint32_t b1) {
    asm volatile(
        "mma.sync.aligned.m16n8k16.row.col.f32.bf16.bf16.f32 "
        "{%0,%1,%2,%3}, {%4,%5,%6,%7}, {%8,%9}, {%0,%1,%2,%3};"
        : "+f"(d[0]), "+f"(d[1]), "+f"(d[2]), "+f"(d[3])
        : "r"(a0), "r"(a1), "r"(a2), "r"(a3), "r"(b0), "r"(b1));
}
__device__ __forceinline__ uint32_t smem_u32(const void* p) {
    uint32_t a;
    asm("{ .reg .u64 t; cvta.to.shared.u64 t, %1; cvt.u32.u64 %0, t; }" : "=r"(a) : "l"(p));
    return a;
}
__device__ __forceinline__ void cp16(uint32_t s, const void* g) {
    asm volatile("cp.async.cg.shared.global [%0], [%1], 16;" :: "r"(s), "l"(g));
}
__device__ __forceinline__ uint32_t pack_bf16(float lo, float hi) {
    __nv_bfloat162 t = __floats2bfloat162_rn(lo, hi);
    return *(uint32_t*)&t;
}

// ---------------- prep: e2 + bf16 hi/lo codebook + reset ----------------
__global__ void prep_kernel(const float* __restrict__ emb) {
    if (blockIdx.x == 0 && threadIdx.x == 0) g_namb = 0;
    int k = blockIdx.x * 256 + threadIdx.x;
    if (k < KCODES) {
        float s = 0.f;
#pragma unroll
        for (int d = 0; d < DIMV; ++d) {
            float v = emb[k * DIMV + d];
            s = fmaf(v, v, s);
            __nv_bfloat16 h = __float2bfloat16(v);
            g_ehi[k * DIMV + d] = h;
            g_elo[k * DIMV + d] = __float2bfloat16(v - __bfloat162float(h));
        }
        g_e2[k] = s;
    }
}

// merge (best,sec,idx) pairs over disjoint code sets; ties force sec=best (-> fixup)
__device__ __forceinline__ void merge_bsi(float& b, float& s, int& i,
                                          float ob, float os, int oi) {
    if (ob < b)      { s = fminf(b, os); b = ob; i = oi; }
    else if (b < ob) { s = fminf(s, ob); }
    else             { i = min(i, oi); s = b; }
}

// ---------------- main screen: HMMA bf16 hi/lo GEMM + argmin ----------------
__global__ __launch_bounds__(THREADS, 1) void vq_kernel(const float* __restrict__ z) {
    extern __shared__ char smem[];
    const uint32_t sb = smem_u32(smem);
    const int tid  = threadIdx.x;
    const int wid  = tid >> 5;
    const int lane = tid & 31;
    const int qr   = lane >> 2;          // 0..7
    const int qc   = lane & 3;           // 0..3

    const int n0 = blockIdx.x * RPB;
    const int b  = n0 >> 12;
    const int hw = n0 & 4095;
    const int zbase = b * 262144 + hw;

    float* zsp = (float*)smem;           // [64][ZS_STRIDE]
    float* csm = (float*)(smem + C_OFF); // [1024]

    // stage z [d][r] fp32, coalesced float4; also C
#pragma unroll
    for (int i = 0; i < 16; ++i) {
        int idx4 = i * THREADS + tid;                    // 4096 float4
        int d = idx4 >> 6, r4 = (idx4 & 63) << 2;
        float4 v = *(const float4*)(z + zbase + d * 4096 + r4);
        *(float4*)&zsp[d * ZS_STRIDE + r4] = v;
    }
#pragma unroll
    for (int i = 0; i < 4; ++i) csm[i * 256 + tid] = g_e2[i * 256 + tid];
    __syncthreads();

    // build A fragments (hi/lo) in registers: warp rows [wid*32, wid*32+32)
    uint32_t ah[2][4][4], al[2][4][4];
#pragma unroll
    for (int mi = 0; mi < 2; ++mi)
#pragma unroll
        for (int ks = 0; ks < 4; ++ks)
#pragma unroll
            for (int rg = 0; rg < 4; ++rg) {
                int r = wid * 32 + mi * 16 + (rg & 1) * 8 + qr;
                int d = ks * 16 + (rg >> 1) * 8 + qc * 2;
                float v0 = zsp[d * ZS_STRIDE + r];
                float v1 = zsp[(d + 1) * ZS_STRIDE + r];
                float h0 = __bfloat162float(__float2bfloat16(v0));
                float h1 = __bfloat162float(__float2bfloat16(v1));
                ah[mi][ks][rg] = pack_bf16(h0, h1);
                al[mi][ks][rg] = pack_bf16(v0 - h0, v1 - h1);
            }
    __syncthreads();   // zstage dead; B bufs may now overwrite it

    // cp.async chunk loader: chunk c (128 codes) -> buf bi; 16B-unit xor swizzle
    auto issue_chunk = [&](int c, int bi) {
        uint32_t hib = sb + bi * 32768;
#pragma unroll
        for (int i = 0; i < 4; ++i) {
            int idx = i * THREADS + tid;                 // 1024 16B units
            int cr = idx >> 3, u = idx & 7;
            uint32_t doff = cr * 128 + ((u ^ (cr & 7)) << 4);
            cp16(hib + doff,         (const char*)g_ehi + c * 16384 + idx * 16);
            cp16(hib + 16384 + doff, (const char*)g_elo + c * 16384 + idx * 16);
        }
        asm volatile("cp.async.commit_group;" ::: "memory");
    };

    issue_chunk(0, 0);
    issue_chunk(1, 1);

    float best[4], sec[4];
    int   bidx[4];
#pragma unroll
    for (int g = 0; g < 4; ++g) { best[g] = 3.4028235e38f; sec[g] = 3.4028235e38f; bidx[g] = 0; }

    for (int c = 0; c < 8; ++c) {
        if (c < 7) asm volatile("cp.async.wait_group 1;" ::: "memory");
        else       asm volatile("cp.async.wait_group 0;" ::: "memory");
        __syncthreads();

        const char* bb = smem + (c & 1) * 32768;
        const int cbase = c * 128;
#pragma unroll
        for (int s = 0; s < 2; ++s) {
            float acc[2][8][4];
#pragma unroll
            for (int mi = 0; mi < 2; ++mi)
#pragma unroll
                for (int a = 0; a < 8; ++a)
#pragma unroll
                    for (int q = 0; q < 4; ++q) acc[mi][a][q] = 0.f;

#pragma unroll
            for (int ks = 0; ks < 4; ++ks) {
#pragma unroll
                for (int a = 0; a < 8; ++a) {
                    uint32_t rowoff = (uint32_t)(s * 64 + a * 8 + qr) * 128 + qc * 4;
                    uint32_t u0 = (uint32_t)(((ks * 2)     ^ qr) << 4);
                    uint32_t u1 = (uint32_t)(((ks * 2 + 1) ^ qr) << 4);
                    uint32_t bh0 = *(const uint32_t*)(bb + rowoff + u0);
                    uint32_t bh1 = *(const uint32_t*)(bb + rowoff + u1);
                    uint32_t bl0 = *(const uint32_t*)(bb + 16384 + rowoff + u0);
                    uint32_t bl1 = *(const uint32_t*)(bb + 16384 + rowoff + u1);
                    mma_bf16(acc[0][a], ah[0][ks][0], ah[0][ks][1], ah[0][ks][2], ah[0][ks][3], bh0, bh1);
                    mma_bf16(acc[1][a], ah[1][ks][0], ah[1][ks][1], ah[1][ks][2], ah[1][ks][3], bh0, bh1);
                    mma_bf16(acc[0][a], al[0][ks][0], al[0][ks][1], al[0][ks][2], al[0][ks][3], bh0, bh1);
                    mma_bf16(acc[1][a], al[1][ks][0], al[1][ks][1], al[1][ks][2], al[1][ks][3], bh0, bh1);
                    mma_bf16(acc[0][a], ah[0][ks][0], ah[0][ks][1], ah[0][ks][2], ah[0][ks][3], bl0, bl1);
                    mma_bf16(acc[1][a], ah[1][ks][0], ah[1][ks][1], ah[1][ks][2], ah[1][ks][3], bl0, bl1);
                }
            }
            // epilogue: score = C_k - 2*dot ; ascending k, strict '<'
#pragma unroll
            for (int a = 0; a < 8; ++a) {
                int k0 = cbase + s * 64 + a * 8 + qc * 2;
                float2 cv = *(const float2*)(smem + C_OFF + k0 * 4);
                float s00 = fmaf(-2.f, acc[0][a][0], cv.x);
                float s01 = fmaf(-2.f, acc[0][a][1], cv.y);
                float s02 = fmaf(-2.f, acc[0][a][2], cv.x);
                float s03 = fmaf(-2.f, acc[0][a][3], cv.y);
                float s10 = fmaf(-2.f, acc[1][a][0], cv.x);
                float s11 = fmaf(-2.f, acc[1][a][1], cv.y);
                float s12 = fmaf(-2.f, acc[1][a][2], cv.x);
                float s13 = fmaf(-2.f, acc[1][a][3], cv.y);
                if (s00 < best[0]) { sec[0] = best[0]; best[0] = s00; bidx[0] = k0; } else if (s00 < sec[0]) sec[0] = s00;
                if (s01 < best[0]) { sec[0] = best[0]; best[0] = s01; bidx[0] = k0 + 1; } else if (s01 < sec[0]) sec[0] = s01;
                if (s02 < best[1]) { sec[1] = best[1]; best[1] = s02; bidx[1] = k0; } else if (s02 < sec[1]) sec[1] = s02;
                if (s03 < best[1]) { sec[1] = best[1]; best[1] = s03; bidx[1] = k0 + 1; } else if (s03 < sec[1]) sec[1] = s03;
                if (s10 < best[2]) { sec[2] = best[2]; best[2] = s10; bidx[2] = k0; } else if (s10 < sec[2]) sec[2] = s10;
                if (s11 < best[2]) { sec[2] = best[2]; best[2] = s11; bidx[2] = k0 + 1; } else if (s11 < sec[2]) sec[2] = s11;
                if (s12 < best[3]) { sec[3] = best[3]; best[3] = s12; bidx[3] = k0; } else if (s12 < sec[3]) sec[3] = s12;
                if (s13 < best[3]) { sec[3] = best[3]; best[3] = s13; bidx[3] = k0 + 1; } else if (s13 < sec[3]) sec[3] = s13;
            }
        }
        __syncthreads();
        if (c + 2 < 8) issue_chunk(c + 2, c & 1);
    }

    // reduce across the 4 lanes (qc) sharing each row
#pragma unroll
    for (int off = 1; off <= 2; off <<= 1) {
#pragma unroll
        for (int g = 0; g < 4; ++g) {
            float ob = __shfl_xor_sync(0xffffffffu, best[g], off);
            float os = __shfl_xor_sync(0xffffffffu, sec[g],  off);
            int   oi = __shfl_xor_sync(0xffffffffu, bidx[g], off);
            merge_bsi(best[g], sec[g], bidx[g], ob, os, oi);
        }
    }
    if (qc == 0) {
#pragma unroll
        for (int g = 0; g < 4; ++g) {
            // g0: +0, g1: +8, g2: +16, g3: +24
            int rl = wid * 32 + ((g >> 1) * 16) + ((g & 1) * 8) + qr;
            int n = n0 + rl;
            g_idx[n] = bidx[g];
            if (sec[g] - best[g] < EPS_GAP) {
                int slot = atomicAdd(&g_namb, 1);
                if (slot < AMB_CAP) g_amb[slot] = n;
            }
        }
    }
}

// ---------------- exact fp64 re-argmin for flagged rows ----------------
__global__ __launch_bounds__(256) void fixup_kernel(
    const float* __restrict__ z, const float* __restrict__ emb)
{
    __shared__ double zrow[DIMV];
    __shared__ double bvs[256];
    __shared__ int    bks[256];
    int namb = g_namb;
    if (namb > AMB_CAP) namb = AMB_CAP;
    for (int i = blockIdx.x; i < namb; i += gridDim.x) {
        int n = g_amb[i];
        int b = n >> 12, hw = n & 4095;
        const float* zp = z + b * 262144 + hw;
        if (threadIdx.x < DIMV) zrow[threadIdx.x] = (double)zp[threadIdx.x * 4096];
        __syncthreads();
        double bv = 1e300; int bk = 0;
        for (int k = threadIdx.x; k < KCODES; k += 256) {
            const float* e = emb + k * DIMV;
            double s = 0.0;
#pragma unroll
            for (int d = 0; d < DIMV; ++d) {
                double diff = zrow[d] - (double)e[d];
                s = fma(diff, diff, s);
            }
            if (s < bv) { bv = s; bk = k; }
        }
        bvs[threadIdx.x] = bv; bks[threadIdx.x] = bk;
        __syncthreads();
        for (int o = 128; o > 0; o >>= 1) {
            if (threadIdx.x < o) {
                double ov = bvs[threadIdx.x + o]; int ok = bks[threadIdx.x + o];
                if (ov < bvs[threadIdx.x] ||
                    (ov == bvs[threadIdx.x] && ok < bks[threadIdx.x])) {
                    bvs[threadIdx.x] = ov; bks[threadIdx.x] = ok;
                }
            }
            __syncthreads();
        }
        if (threadIdx.x == 0) g_idx[n] = bks[0];
        __syncthreads();
    }
}

// ---------------- gather + output + loss partials ----------------
__global__ __launch_bounds__(THREADS) void out_loss_kernel(
    const float* __restrict__ z, const float* __restrict__ emb,
    float* __restrict__ out)
{
    __shared__ int   ks[128];
    __shared__ float qs[128 * 65];
    __shared__ float wsum[8];
    const int tid = threadIdx.x;
    const int wid = tid >> 5, lane = tid & 31;
    const int n0 = blockIdx.x * 128;
    const int b  = n0 >> 12;
    const int hw = n0 & 4095;
    const int zbase = b * 262144 + hw;

    if (tid < 128) ks[tid] = g_idx[n0 + tid];
    __syncthreads();
    for (int rr = wid; rr < 128; rr += 8) {
        float2 e2v = ((const float2*)(emb + ks[rr] * DIMV))[lane];
        qs[rr * 65 + lane * 2]     = e2v.x;
        qs[rr * 65 + lane * 2 + 1] = e2v.y;
    }
    __syncthreads();

    float lsum = 0.f;
#pragma unroll
    for (int i = 0; i < 32; ++i) {
        int idx = i * THREADS + tid;
        int d = idx >> 7, r = idx & 127;
        float q = qs[r * 65 + d];
        int g = zbase + d * 4096 + r;
        out[g] = q;
        float diff = q - __ldg(&z[g]);
        lsum = fmaf(diff, diff, lsum);
    }
#pragma unroll
    for (int o = 16; o > 0; o >>= 1)
        lsum += __shfl_down_sync(0xffffffffu, lsum, o);
    if ((tid & 31) == 0) wsum[tid >> 5] = lsum;
    __syncthreads();
    if (tid == 0) {
        float s = 0.f;
#pragma unroll
        for (int w = 0; w < 8; ++w) s += wsum[w];
        g_part[blockIdx.x] = s;
    }
}

__global__ void loss_kernel(float* __restrict__ out, int loss_off) {
    __shared__ float s[256];
    int t = threadIdx.x;
    s[t] = g_part[t] + g_part[t + 256] + g_part[t + 512] + g_part[t + 768];
    __syncthreads();
    for (int o = 128; o > 0; o >>= 1) {
        if (t < o) s[t] += s[t + o];
        __syncthreads();
    }
    if (t == 0) {
        float m = s[0] * (1.0f / 8388608.0f);
        out[loss_off] = fmaf(0.25f, m, m);
    }
}

extern "C" void kernel_launch(void* const* d_in, const int* in_sizes, int n_in,
                              void* d_out, int out_size) {
    const float* z   = (const float*)d_in[0];
    const float* emb = (const float*)d_in[1];
    float* out = (float*)d_out;
    cudaFuncSetAttribute(vq_kernel, cudaFuncAttributeMaxDynamicSharedMemorySize, SMEM_VQ);
    prep_kernel<<<4, 256>>>(emb);
    vq_kernel<<<NBLOCKS, THREADS, SMEM_VQ>>>(z);
    fixup_kernel<<<1024, 256>>>(z, emb);
    out_loss_kernel<<<1024, THREADS>>>(z, emb, out);
    loss_kernel<<<1, 256>>>(out, out_size - 1);
}

// round 9
// speedup vs baseline: 1.0927x; 1.0921x over previous
#include <cuda_runtime.h>
#include <cuda_bf16.h>
#include <cstdint>

#define N_ROWS   131072
#define KCODES   1024
#define DIMV     64
#define RPB      256                 // rows per vq CTA
#define NBLOCKS  (N_ROWS / RPB)      // 512
#define THREADS  256
#define EPS_GAP  1.5e-2f
#define PRUNE_W  4e-3f
#define CAND_CAP 128
#define AMB_CAP  131072

// vq smem: zstage fp32 [64][260] = 66560B (overlaid later by B chunk bufs),
// C[1024] fp32 at 66560. B bufs: buf0 hi@0 lo@16384, buf1 hi@32768 lo@49152.
#define ZS_STRIDE 260
#define C_OFF     66560
#define SMEM_VQ   (66560 + 4096)

__device__ float          g_e2[KCODES];
__device__ __nv_bfloat16  g_ehi[KCODES * DIMV];
__device__ __nv_bfloat16  g_elo[KCODES * DIMV];
__device__ float          g_part[1024];
__device__ int            g_idx[N_ROWS];
__device__ int            g_amb[AMB_CAP];
__device__ int            g_namb;

// ---------------- helpers ----------------
__device__ __forceinline__ void mma_bf16(float* d, uint32_t a0, uint32_t a1,
                                         uint32_t a2, uint32_t a3,
                                         uint32_t b0, uint32_t b1) {
    asm volatile(
        "mma.sync.aligned.m16n8k16.row.col.f32.bf16.bf16.f32 "
        "{%0,%1,%2,%3}, {%4,%5,%6,%7}, {%8,%9}, {%0,%1,%2,%3};"
        : "+f"(d[0]), "+f"(d[1]), "+f"(d[2]), "+f"(d[3])
        : "r"(a0), "r"(a1), "r"(a2), "r"(a3), "r"(b0), "r"(b1));
}
__device__ __forceinline__ uint32_t smem_u32(const void* p) {
    uint32_t a;
    asm("{ .reg .u64 t; cvta.to.shared.u64 t, %1; cvt.u32.u64 %0, t; }" : "=r"(a) : "l"(p));
    return a;
}
__device__ __forceinline__ void cp16(uint32_t s, const void* g) {
    asm volatile("cp.async.cg.shared.global [%0], [%1], 16;" :: "r"(s), "l"(g));
}
__device__ __forceinline__ uint32_t pack_bf16(float lo, float hi) {
    __nv_bfloat162 t = __floats2bfloat162_rn(lo, hi);
    return *(uint32_t*)&t;
}

// ---------------- prep: e2 + bf16 hi/lo codebook + reset ----------------
__global__ void prep_kernel(const float* __restrict__ emb) {
    if (blockIdx.x == 0 && threadIdx.x == 0) g_namb = 0;
    int k = blockIdx.x * 256 + threadIdx.x;
    if (k < KCODES) {
        float s = 0.f;
#pragma unroll
        for (int d = 0; d < DIMV; ++d) {
            float v = emb[k * DIMV + d];
            s = fmaf(v, v, s);
            __nv_bfloat16 h = __float2bfloat16(v);
            g_ehi[k * DIMV + d] = h;
            g_elo[k * DIMV + d] = __float2bfloat16(v - __bfloat162float(h));
        }
        g_e2[k] = s;
    }
}

// merge (best,sec,idx) pairs over disjoint code sets; ties force sec=best (-> fixup)
__device__ __forceinline__ void merge_bsi(float& b, float& s, int& i,
                                          float ob, float os, int oi) {
    if (ob < b)      { s = fminf(b, os); b = ob; i = oi; }
    else if (b < ob) { s = fminf(s, ob); }
    else             { i = min(i, oi); s = b; }
}

// ---------------- main screen: HMMA bf16 hi/lo GEMM + argmin ----------------
__global__ __launch_bounds__(THREADS, 1) void vq_kernel(const float* __restrict__ z) {
    extern __shared__ char smem[];
    const uint32_t sb = smem_u32(smem);
    const int tid  = threadIdx.x;
    const int wid  = tid >> 5;
    const int lane = tid & 31;
    const int qr   = lane >> 2;          // 0..7
    const int qc   = lane & 3;           // 0..3

    const int n0 = blockIdx.x * RPB;
    const int b  = n0 >> 12;
    const int hw = n0 & 4095;
    const int zbase = b * 262144 + hw;

    float* zsp = (float*)smem;           // [64][ZS_STRIDE]
    float* csm = (float*)(smem + C_OFF); // [1024]

    // stage z [d][r] fp32, coalesced float4; also C
#pragma unroll
    for (int i = 0; i < 16; ++i) {
        int idx4 = i * THREADS + tid;                    // 4096 float4
        int d = idx4 >> 6, r4 = (idx4 & 63) << 2;
        float4 v = *(const float4*)(z + zbase + d * 4096 + r4);
        *(float4*)&zsp[d * ZS_STRIDE + r4] = v;
    }
#pragma unroll
    for (int i = 0; i < 4; ++i) csm[i * 256 + tid] = g_e2[i * 256 + tid];
    __syncthreads();

    // build A fragments (hi/lo) in registers: warp rows [wid*32, wid*32+32)
    uint32_t ah[2][4][4], al[2][4][4];
#pragma unroll
    for (int mi = 0; mi < 2; ++mi)
#pragma unroll
        for (int ks = 0; ks < 4; ++ks)
#pragma unroll
            for (int rg = 0; rg < 4; ++rg) {
                int r = wid * 32 + mi * 16 + (rg & 1) * 8 + qr;
                int d = ks * 16 + (rg >> 1) * 8 + qc * 2;
                float v0 = zsp[d * ZS_STRIDE + r];
                float v1 = zsp[(d + 1) * ZS_STRIDE + r];
                float h0 = __bfloat162float(__float2bfloat16(v0));
                float h1 = __bfloat162float(__float2bfloat16(v1));
                ah[mi][ks][rg] = pack_bf16(h0, h1);
                al[mi][ks][rg] = pack_bf16(v0 - h0, v1 - h1);
            }
    __syncthreads();   // zstage dead; B bufs may now overwrite it

    // cp.async chunk loader: chunk c (128 codes) -> buf bi; 16B-unit xor swizzle
    auto issue_chunk = [&](int c, int bi) {
        uint32_t hib = sb + bi * 32768;
#pragma unroll
        for (int i = 0; i < 4; ++i) {
            int idx = i * THREADS + tid;                 // 1024 16B units
            int cr = idx >> 3, u = idx & 7;
            uint32_t doff = cr * 128 + ((u ^ (cr & 7)) << 4);
            cp16(hib + doff,         (const char*)g_ehi + c * 16384 + idx * 16);
            cp16(hib + 16384 + doff, (const char*)g_elo + c * 16384 + idx * 16);
        }
        asm volatile("cp.async.commit_group;" ::: "memory");
    };

    issue_chunk(0, 0);
    issue_chunk(1, 1);

    float best[4], sec[4];
    int   bidx[4];
#pragma unroll
    for (int g = 0; g < 4; ++g) { best[g] = 3.4028235e38f; sec[g] = 3.4028235e38f; bidx[g] = 0; }

    for (int c = 0; c < 8; ++c) {
        if (c < 7) asm volatile("cp.async.wait_group 1;" ::: "memory");
        else       asm volatile("cp.async.wait_group 0;" ::: "memory");
        __syncthreads();

        const char* bb = smem + (c & 1) * 32768;
        const int cbase = c * 128;
#pragma unroll
        for (int s = 0; s < 2; ++s) {
            float acc[2][8][4];
#pragma unroll
            for (int mi = 0; mi < 2; ++mi)
#pragma unroll
                for (int a = 0; a < 8; ++a)
#pragma unroll
                    for (int q = 0; q < 4; ++q) acc[mi][a][q] = 0.f;

#pragma unroll
            for (int ks = 0; ks < 4; ++ks) {
#pragma unroll
                for (int a = 0; a < 8; ++a) {
                    uint32_t rowoff = (uint32_t)(s * 64 + a * 8 + qr) * 128 + qc * 4;
                    uint32_t u0 = (uint32_t)(((ks * 2)     ^ qr) << 4);
                    uint32_t u1 = (uint32_t)(((ks * 2 + 1) ^ qr) << 4);
                    uint32_t bh0 = *(const uint32_t*)(bb + rowoff + u0);
                    uint32_t bh1 = *(const uint32_t*)(bb + rowoff + u1);
                    uint32_t bl0 = *(const uint32_t*)(bb + 16384 + rowoff + u0);
                    uint32_t bl1 = *(const uint32_t*)(bb + 16384 + rowoff + u1);
                    mma_bf16(acc[0][a], ah[0][ks][0], ah[0][ks][1], ah[0][ks][2], ah[0][ks][3], bh0, bh1);
                    mma_bf16(acc[1][a], ah[1][ks][0], ah[1][ks][1], ah[1][ks][2], ah[1][ks][3], bh0, bh1);
                    mma_bf16(acc[0][a], al[0][ks][0], al[0][ks][1], al[0][ks][2], al[0][ks][3], bh0, bh1);
                    mma_bf16(acc[1][a], al[1][ks][0], al[1][ks][1], al[1][ks][2], al[1][ks][3], bh0, bh1);
                    mma_bf16(acc[0][a], ah[0][ks][0], ah[0][ks][1], ah[0][ks][2], ah[0][ks][3], bl0, bl1);
                    mma_bf16(acc[1][a], ah[1][ks][0], ah[1][ks][1], ah[1][ks][2], ah[1][ks][3], bl0, bl1);
                }
            }
            // epilogue: score = C_k - 2*dot ; ascending k, strict '<'
#pragma unroll
            for (int a = 0; a < 8; ++a) {
                int k0 = cbase + s * 64 + a * 8 + qc * 2;
                float2 cv = *(const float2*)(smem + C_OFF + k0 * 4);
                float s00 = fmaf(-2.f, acc[0][a][0], cv.x);
                float s01 = fmaf(-2.f, acc[0][a][1], cv.y);
                float s02 = fmaf(-2.f, acc[0][a][2], cv.x);
                float s03 = fmaf(-2.f, acc[0][a][3], cv.y);
                float s10 = fmaf(-2.f, acc[1][a][0], cv.x);
                float s11 = fmaf(-2.f, acc[1][a][1], cv.y);
                float s12 = fmaf(-2.f, acc[1][a][2], cv.x);
                float s13 = fmaf(-2.f, acc[1][a][3], cv.y);
                if (s00 < best[0]) { sec[0] = best[0]; best[0] = s00; bidx[0] = k0; } else if (s00 < sec[0]) sec[0] = s00;
                if (s01 < best[0]) { sec[0] = best[0]; best[0] = s01; bidx[0] = k0 + 1; } else if (s01 < sec[0]) sec[0] = s01;
                if (s02 < best[1]) { sec[1] = best[1]; best[1] = s02; bidx[1] = k0; } else if (s02 < sec[1]) sec[1] = s02;
                if (s03 < best[1]) { sec[1] = best[1]; best[1] = s03; bidx[1] = k0 + 1; } else if (s03 < sec[1]) sec[1] = s03;
                if (s10 < best[2]) { sec[2] = best[2]; best[2] = s10; bidx[2] = k0; } else if (s10 < sec[2]) sec[2] = s10;
                if (s11 < best[2]) { sec[2] = best[2]; best[2] = s11; bidx[2] = k0 + 1; } else if (s11 < sec[2]) sec[2] = s11;
                if (s12 < best[3]) { sec[3] = best[3]; best[3] = s12; bidx[3] = k0; } else if (s12 < sec[3]) sec[3] = s12;
                if (s13 < best[3]) { sec[3] = best[3]; best[3] = s13; bidx[3] = k0 + 1; } else if (s13 < sec[3]) sec[3] = s13;
            }
        }
        __syncthreads();
        if (c + 2 < 8) issue_chunk(c + 2, c & 1);
    }

    // reduce across the 4 lanes (qc) sharing each row
#pragma unroll
    for (int off = 1; off <= 2; off <<= 1) {
#pragma unroll
        for (int g = 0; g < 4; ++g) {
            float ob = __shfl_xor_sync(0xffffffffu, best[g], off);
            float os = __shfl_xor_sync(0xffffffffu, sec[g],  off);
            int   oi = __shfl_xor_sync(0xffffffffu, bidx[g], off);
            merge_bsi(best[g], sec[g], bidx[g], ob, os, oi);
        }
    }
    if (qc == 0) {
#pragma unroll
        for (int g = 0; g < 4; ++g) {
            // g0: +0, g1: +8, g2: +16, g3: +24
            int rl = wid * 32 + ((g >> 1) * 16) + ((g & 1) * 8) + qr;
            int n = n0 + rl;
            g_idx[n] = bidx[g];
            if (sec[g] - best[g] < EPS_GAP) {
                int slot = atomicAdd(&g_namb, 1);
                if (slot < AMB_CAP) g_amb[slot] = n;
            }
        }
    }
}

// ---------------- pruned fixup: fp32 scan -> candidate set -> fp64 decide ----------------
__global__ __launch_bounds__(256) void fixup_kernel(
    const float* __restrict__ z, const float* __restrict__ emb)
{
    __shared__ float  zrow[DIMV];
    __shared__ float  mins[256];
    __shared__ int    cand[CAND_CAP];
    __shared__ int    ncand;
    __shared__ double cd[CAND_CAP];
    int namb = g_namb;
    if (namb > AMB_CAP) namb = AMB_CAP;
    for (int i = blockIdx.x; i < namb; i += gridDim.x) {
        int n = g_amb[i];
        int b = n >> 12, hw = n & 4095;
        const float* zp = z + b * 262144 + hw;
        if (threadIdx.x < DIMV) zrow[threadIdx.x] = zp[threadIdx.x * 4096];
        if (threadIdx.x == 0) ncand = 0;
        __syncthreads();

        // pass 1: fp32 direct distances, 4 codes per thread, keep in regs
        float dv[4];
        float lmin = 3.4028235e38f;
#pragma unroll
        for (int j = 0; j < 4; ++j) {
            int k = j * 256 + threadIdx.x;
            const float* e = emb + k * DIMV;
            float s = 0.f;
#pragma unroll
            for (int d = 0; d < DIMV; ++d) {
                float diff = zrow[d] - e[d];
                s = fmaf(diff, diff, s);
            }
            dv[j] = s;
            lmin = fminf(lmin, s);
        }
        mins[threadIdx.x] = lmin;
        __syncthreads();
        for (int o = 128; o > 0; o >>= 1) {
            if (threadIdx.x < o)
                mins[threadIdx.x] = fminf(mins[threadIdx.x], mins[threadIdx.x + o]);
            __syncthreads();
        }
        float bmin = mins[0];

        // pass 2: collect candidates within window
#pragma unroll
        for (int j = 0; j < 4; ++j) {
            if (dv[j] < bmin + PRUNE_W) {
                int slot = atomicAdd(&ncand, 1);
                if (slot < CAND_CAP) cand[slot] = j * 256 + threadIdx.x;
            }
        }
        __syncthreads();
        int nc = min(ncand, CAND_CAP);

        // pass 3: fp64 exact distance per candidate (one thread each)
        if (threadIdx.x < nc) {
            int k = cand[threadIdx.x];
            const float* e = emb + k * DIMV;
            double s = 0.0;
#pragma unroll
            for (int d = 0; d < DIMV; ++d) {
                double diff = (double)zrow[d] - (double)e[d];
                s = fma(diff, diff, s);
            }
            cd[threadIdx.x] = s;
        }
        __syncthreads();

        // lex-(value, k) argmin over candidates (order-independent)
        if (threadIdx.x == 0) {
            double bv = 1e300; int bk = 0x7fffffff;
            for (int t = 0; t < nc; ++t) {
                double v = cd[t]; int kk = cand[t];
                if (v < bv || (v == bv && kk < bk)) { bv = v; bk = kk; }
            }
            g_idx[n] = bk;
        }
        __syncthreads();
    }
}

// ---------------- gather + output + loss partials ----------------
__global__ __launch_bounds__(THREADS) void out_loss_kernel(
    const float* __restrict__ z, const float* __restrict__ emb,
    float* __restrict__ out)
{
    __shared__ int   ks[128];
    __shared__ float qs[128 * 65];
    __shared__ float wsum[8];
    const int tid = threadIdx.x;
    const int wid = tid >> 5, lane = tid & 31;
    const int n0 = blockIdx.x * 128;
    const int b  = n0 >> 12;
    const int hw = n0 & 4095;
    const int zbase = b * 262144 + hw;

    if (tid < 128) ks[tid] = g_idx[n0 + tid];
    __syncthreads();
    for (int rr = wid; rr < 128; rr += 8) {
        float2 e2v = ((const float2*)(emb + ks[rr] * DIMV))[lane];
        qs[rr * 65 + lane * 2]     = e2v.x;
        qs[rr * 65 + lane * 2 + 1] = e2v.y;
    }
    __syncthreads();

    float lsum = 0.f;
#pragma unroll
    for (int i = 0; i < 32; ++i) {
        int idx = i * THREADS + tid;
        int d = idx >> 7, r = idx & 127;
        float q = qs[r * 65 + d];
        int g = zbase + d * 4096 + r;
        out[g] = q;
        float diff = q - __ldg(&z[g]);
        lsum = fmaf(diff, diff, lsum);
    }
#pragma unroll
    for (int o = 16; o > 0; o >>= 1)
        lsum += __shfl_down_sync(0xffffffffu, lsum, o);
    if ((tid & 31) == 0) wsum[tid >> 5] = lsum;
    __syncthreads();
    if (tid == 0) {
        float s = 0.f;
#pragma unroll
        for (int w = 0; w < 8; ++w) s += wsum[w];
        g_part[blockIdx.x] = s;
    }
}

__global__ void loss_kernel(float* __restrict__ out, int loss_off) {
    __shared__ float s[256];
    int t = threadIdx.x;
    s[t] = g_part[t] + g_part[t + 256] + g_part[t + 512] + g_part[t + 768];
    __syncthreads();
    for (int o = 128; o > 0; o >>= 1) {
        if (t < o) s[t] += s[t + o];
        __syncthreads();
    }
    if (t == 0) {
        float m = s[0] * (1.0f / 8388608.0f);
        out[loss_off] = fmaf(0.25f, m, m);
    }
}

extern "C" void kernel_launch(void* const* d_in, const int* in_sizes, int n_in,
                              void* d_out, int out_size) {
    const float* z   = (const float*)d_in[0];
    const float* emb = (const float*)d_in[1];
    float* out = (float*)d_out;
    cudaFuncSetAttribute(vq_kernel, cudaFuncAttributeMaxDynamicSharedMemorySize, SMEM_VQ);
    prep_kernel<<<4, 256>>>(emb);
    vq_kernel<<<NBLOCKS, THREADS, SMEM_VQ>>>(z);
    fixup_kernel<<<1024, 256>>>(z, emb);
    out_loss_kernel<<<1024, THREADS>>>(z, emb, out);
    loss_kernel<<<1, 256>>>(out, out_size - 1);
}

// round 12
// speedup vs baseline: 1.2799x; 1.1712x over previous
#include <cuda_runtime.h>
#include <cuda_fp16.h>
#include <cstdint>

#define N_ROWS   131072
#define KCODES   1024
#define DIMV     64
#define RPB      128                 // rows per vq CTA
#define NBLOCKS  (N_ROWS / RPB)      // 1024
#define THREADS  256
#define EPS_GAP  2.5e-2f
#define PRUNE_W  4e-3f
#define CAND_CAP 128
#define AMB_CAP  131072

// vq smem: B0 16K @0, B1 16K @16384 (both overlay the fp32 z stage used in the
// prologue: zstage [64][132] fp32 = 33792B @0), C[1024] fp32 @33792.
#define ZS_STRIDE 132
#define C_OFF     33792
#define SMEM_VQ   (33792 + 4096)

__device__ float   g_e2[KCODES];
__device__ __half  g_ehi[KCODES * DIMV];
__device__ float   g_part[1024];
__device__ int     g_idx[N_ROWS];
__device__ int     g_amb[AMB_CAP];
__device__ int     g_namb;

// ---------------- helpers ----------------
__device__ __forceinline__ void mma_f16(float* d, uint32_t a0, uint32_t a1,
                                        uint32_t a2, uint32_t a3,
                                        uint32_t b0, uint32_t b1) {
    asm volatile(
        "mma.sync.aligned.m16n8k16.row.col.f32.f16.f16.f32 "
        "{%0,%1,%2,%3}, {%4,%5,%6,%7}, {%8,%9}, {%0,%1,%2,%3};"
        : "+f"(d[0]), "+f"(d[1]), "+f"(d[2]), "+f"(d[3])
        : "r"(a0), "r"(a1), "r"(a2), "r"(a3), "r"(b0), "r"(b1));
}
__device__ __forceinline__ uint32_t smem_u32(const void* p) {
    uint32_t a;
    asm("{ .reg .u64 t; cvta.to.shared.u64 t, %1; cvt.u32.u64 %0, t; }" : "=r"(a) : "l"(p));
    return a;
}
__device__ __forceinline__ void cp16(uint32_t s, const void* g) {
    asm volatile("cp.async.cg.shared.global [%0], [%1], 16;" :: "r"(s), "l"(g));
}
__device__ __forceinline__ uint32_t pack_h2(float lo, float hi) {
    __half2 t = __floats2half2_rn(lo, hi);
    return *(uint32_t*)&t;
}

// ---------------- prep: e2 + fp16 codebook + reset ----------------
__global__ void prep_kernel(const float* __restrict__ emb) {
    if (blockIdx.x == 0 && threadIdx.x == 0) g_namb = 0;
    int k = blockIdx.x * 256 + threadIdx.x;
    if (k < KCODES) {
        float s = 0.f;
#pragma unroll
        for (int d = 0; d < DIMV; ++d) {
            float v = emb[k * DIMV + d];
            s = fmaf(v, v, s);
            g_ehi[k * DIMV + d] = __float2half_rn(v);
        }
        g_e2[k] = s;
    }
}

// merge (best,sec,idx) over disjoint code sets; ties force sec=best (-> fixup)
__device__ __forceinline__ void merge_bsi(float& b, float& s, int& i,
                                          float ob, float os, int oi) {
    if (ob < b)      { s = fminf(b, os); b = ob; i = oi; }
    else if (b < ob) { s = fminf(s, ob); }
    else             { i = min(i, oi); s = b; }
}

// ---------------- main screen: 2-pass fp16 HMMA + argmin ----------------
__global__ __launch_bounds__(THREADS, 2) void vq_kernel(const float* __restrict__ z) {
    extern __shared__ char smem[];
    const uint32_t sb = smem_u32(smem);
    const int tid  = threadIdx.x;
    const int wid  = tid >> 5;
    const int lane = tid & 31;
    const int qr   = lane >> 2;          // 0..7
    const int qc   = lane & 3;           // 0..3

    const int n0 = blockIdx.x * RPB;
    const int b  = n0 >> 12;
    const int hw = n0 & 4095;
    const int zbase = b * 262144 + hw;

    float* zsp = (float*)smem;           // [64][ZS_STRIDE], prologue only

    // stage z [d][r] fp32, coalesced float4 (128 rows x 64 d = 2048 float4)
#pragma unroll
    for (int i = 0; i < 8; ++i) {
        int idx4 = i * THREADS + tid;
        int d = idx4 >> 5, r4 = (idx4 & 31) << 2;
        float4 v = *(const float4*)(z + zbase + d * 4096 + r4);
        *(float4*)&zsp[d * ZS_STRIDE + r4] = v;
    }
    __syncthreads();

    // build A fragments (hi/lo fp16) in regs: warp owns rows [wid*16, wid*16+16)
    uint32_t ah[4][4], al[4][4];
#pragma unroll
    for (int ks = 0; ks < 4; ++ks)
#pragma unroll
        for (int rg = 0; rg < 4; ++rg) {
            int r = wid * 16 + (rg & 1) * 8 + qr;
            int d = ks * 16 + (rg >> 1) * 8 + qc * 2;
            float v0 = zsp[d * ZS_STRIDE + r];
            float v1 = zsp[(d + 1) * ZS_STRIDE + r];
            float h0 = __half2float(__float2half_rn(v0));
            float h1 = __half2float(__float2half_rn(v1));
            ah[ks][rg] = pack_h2(h0, h1);
            al[ks][rg] = pack_h2(v0 - h0, v1 - h1);
        }
    __syncthreads();   // zstage dead; B bufs overwrite it

    // load C (e2) into smem
    float* csm = (float*)(smem + C_OFF);
#pragma unroll
    for (int i = 0; i < 4; ++i) csm[i * 256 + tid] = g_e2[i * 256 + tid];

    // cp.async chunk loader: chunk c (128 codes x 64 fp16 = 16KB) -> buf bi
    auto issue_chunk = [&](int c, int bi) {
        uint32_t bbuf = sb + bi * 16384;
#pragma unroll
        for (int i = 0; i < 4; ++i) {
            int idx = i * THREADS + tid;                 // 1024 16B units
            int cr = idx >> 3, u = idx & 7;
            uint32_t doff = cr * 128 + ((u ^ (cr & 7)) << 4);
            cp16(bbuf + doff, (const char*)g_ehi + c * 16384 + idx * 16);
        }
        asm volatile("cp.async.commit_group;" ::: "memory");
    };

    issue_chunk(0, 0);
    issue_chunk(1, 1);

    float best[2], sec[2];
    int   bidx[2];
#pragma unroll
    for (int g = 0; g < 2; ++g) { best[g] = 3.4028235e38f; sec[g] = 3.4028235e38f; bidx[g] = 0; }

    for (int c = 0; c < 8; ++c) {
        if (c < 7) asm volatile("cp.async.wait_group 1;" ::: "memory");
        else       asm volatile("cp.async.wait_group 0;" ::: "memory");
        __syncthreads();

        const char* bb = smem + (c & 1) * 16384;
        const int cbase = c * 128;
#pragma unroll
        for (int s = 0; s < 2; ++s) {
            float acc[8][4];
#pragma unroll
            for (int a = 0; a < 8; ++a)
#pragma unroll
                for (int q = 0; q < 4; ++q) acc[a][q] = 0.f;

#pragma unroll
            for (int ks = 0; ks < 4; ++ks) {
#pragma unroll
                for (int a = 0; a < 8; ++a) {
                    uint32_t rowoff = (uint32_t)(s * 64 + a * 8 + qr) * 128 + qc * 4;
                    uint32_t u0 = (uint32_t)(((ks * 2)     ^ qr) << 4);
                    uint32_t u1 = (uint32_t)(((ks * 2 + 1) ^ qr) << 4);
                    uint32_t b0 = *(const uint32_t*)(bb + rowoff + u0);
                    uint32_t b1 = *(const uint32_t*)(bb + rowoff + u1);
                    mma_f16(acc[a], ah[ks][0], ah[ks][1], ah[ks][2], ah[ks][3], b0, b1);
                    mma_f16(acc[a], al[ks][0], al[ks][1], al[ks][2], al[ks][3], b0, b1);
                }
            }
            // epilogue: score = C_k - 2*dot ; ascending k, strict '<'
#pragma unroll
            for (int a = 0; a < 8; ++a) {
                int k0 = cbase + s * 64 + a * 8 + qc * 2;
                float2 cv = *(const float2*)(smem + C_OFF + k0 * 4);
                float s00 = fmaf(-2.f, acc[a][0], cv.x);   // row qr,   col k0
                float s01 = fmaf(-2.f, acc[a][1], cv.y);   // row qr,   col k0+1
                float s10 = fmaf(-2.f, acc[a][2], cv.x);   // row qr+8, col k0
                float s11 = fmaf(-2.f, acc[a][3], cv.y);   // row qr+8, col k0+1
                if (s00 < best[0]) { sec[0] = best[0]; best[0] = s00; bidx[0] = k0; } else if (s00 < sec[0]) sec[0] = s00;
                if (s01 < best[0]) { sec[0] = best[0]; best[0] = s01; bidx[0] = k0 + 1; } else if (s01 < sec[0]) sec[0] = s01;
                if (s10 < best[1]) { sec[1] = best[1]; best[1] = s10; bidx[1] = k0; } else if (s10 < sec[1]) sec[1] = s10;
                if (s11 < best[1]) { sec[1] = best[1]; best[1] = s11; bidx[1] = k0 + 1; } else if (s11 < sec[1]) sec[1] = s11;
            }
        }
        __syncthreads();
        if (c + 2 < 8) issue_chunk(c + 2, c & 1);
    }

    // reduce across the 4 qc lanes sharing each row
#pragma unroll
    for (int off = 1; off <= 2; off <<= 1) {
#pragma unroll
        for (int g = 0; g < 2; ++g) {
            float ob = __shfl_xor_sync(0xffffffffu, best[g], off);
            float os = __shfl_xor_sync(0xffffffffu, sec[g],  off);
            int   oi = __shfl_xor_sync(0xffffffffu, bidx[g], off);
            merge_bsi(best[g], sec[g], bidx[g], ob, os, oi);
        }
    }
    if (qc == 0) {
#pragma unroll
        for (int g = 0; g < 2; ++g) {
            int n = n0 + wid * 16 + g * 8 + qr;
            g_idx[n] = bidx[g];
            if (sec[g] - best[g] < EPS_GAP) {
                int slot = atomicAdd(&g_namb, 1);
                if (slot < AMB_CAP) g_amb[slot] = n;
            }
        }
    }
}

// ---------------- pruned fixup: fp32 scan -> candidate set -> fp64 decide ----------------
__global__ __launch_bounds__(256) void fixup_kernel(
    const float* __restrict__ z, const float* __restrict__ emb)
{
    __shared__ float  zrow[DIMV];
    __shared__ float  mins[256];
    __shared__ int    cand[CAND_CAP];
    __shared__ int    ncand;
    __shared__ double cd[CAND_CAP];
    int namb = g_namb;
    if (namb > AMB_CAP) namb = AMB_CAP;
    for (int i = blockIdx.x; i < namb; i += gridDim.x) {
        int n = g_amb[i];
        int b = n >> 12, hw = n & 4095;
        const float* zp = z + b * 262144 + hw;
        if (threadIdx.x < DIMV) zrow[threadIdx.x] = zp[threadIdx.x * 4096];
        if (threadIdx.x == 0) ncand = 0;
        __syncthreads();

        float dv[4];
        float lmin = 3.4028235e38f;
#pragma unroll
        for (int j = 0; j < 4; ++j) {
            int k = j * 256 + threadIdx.x;
            const float* e = emb + k * DIMV;
            float s = 0.f;
#pragma unroll
            for (int d = 0; d < DIMV; ++d) {
                float diff = zrow[d] - e[d];
                s = fmaf(diff, diff, s);
            }
            dv[j] = s;
            lmin = fminf(lmin, s);
        }
        mins[threadIdx.x] = lmin;
        __syncthreads();
        for (int o = 128; o > 0; o >>= 1) {
            if (threadIdx.x < o)
                mins[threadIdx.x] = fminf(mins[threadIdx.x], mins[threadIdx.x + o]);
            __syncthreads();
        }
        float bmin = mins[0];

#pragma unroll
        for (int j = 0; j < 4; ++j) {
            if (dv[j] < bmin + PRUNE_W) {
                int slot = atomicAdd(&ncand, 1);
                if (slot < CAND_CAP) cand[slot] = j * 256 + threadIdx.x;
            }
        }
        __syncthreads();
        int nc = min(ncand, CAND_CAP);

        if (threadIdx.x < nc) {
            int k = cand[threadIdx.x];
            const float* e = emb + k * DIMV;
            double s = 0.0;
#pragma unroll
            for (int d = 0; d < DIMV; ++d) {
                double diff = (double)zrow[d] - (double)e[d];
                s = fma(diff, diff, s);
            }
            cd[threadIdx.x] = s;
        }
        __syncthreads();

        if (threadIdx.x == 0) {
            double bv = 1e300; int bk = 0x7fffffff;
            for (int t = 0; t < nc; ++t) {
                double v = cd[t]; int kk = cand[t];
                if (v < bv || (v == bv && kk < bk)) { bv = v; bk = kk; }
            }
            g_idx[n] = bk;
        }
        __syncthreads();
    }
}

// ---------------- gather + output + loss partials ----------------
__global__ __launch_bounds__(THREADS) void out_loss_kernel(
    const float* __restrict__ z, const float* __restrict__ emb,
    float* __restrict__ out)
{
    __shared__ int   ks[128];
    __shared__ float qs[128 * 65];
    __shared__ float wsum[8];
    const int tid = threadIdx.x;
    const int wid = tid >> 5, lane = tid & 31;
    const int n0 = blockIdx.x * 128;
    const int b  = n0 >> 12;
    const int hw = n0 & 4095;
    const int zbase = b * 262144 + hw;

    if (tid < 128) ks[tid] = g_idx[n0 + tid];
    __syncthreads();
    for (int rr = wid; rr < 128; rr += 8) {
        float2 e2v = ((const float2*)(emb + ks[rr] * DIMV))[lane];
        qs[rr * 65 + lane * 2]     = e2v.x;
        qs[rr * 65 + lane * 2 + 1] = e2v.y;
    }
    __syncthreads();

    float lsum = 0.f;
#pragma unroll
    for (int i = 0; i < 32; ++i) {
        int idx = i * THREADS + tid;
        int d = idx >> 7, r = idx & 127;
        float q = qs[r * 65 + d];
        int g = zbase + d * 4096 + r;
        out[g] = q;
        float diff = q - __ldg(&z[g]);
        lsum = fmaf(diff, diff, lsum);
    }
#pragma unroll
    for (int o = 16; o > 0; o >>= 1)
        lsum += __shfl_down_sync(0xffffffffu, lsum, o);
    if ((tid & 31) == 0) wsum[tid >> 5] = lsum;
    __syncthreads();
    if (tid == 0) {
        float s = 0.f;
#pragma unroll
        for (int w = 0; w < 8; ++w) s += wsum[w];
        g_part[blockIdx.x] = s;
    }
}

__global__ void loss_kernel(float* __restrict__ out, int loss_off) {
    __shared__ float s[256];
    int t = threadIdx.x;
    s[t] = g_part[t] + g_part[t + 256] + g_part[t + 512] + g_part[t + 768];
    __syncthreads();
    for (int o = 128; o > 0; o >>= 1) {
        if (t < o) s[t] += s[t + o];
        __syncthreads();
    }
    if (t == 0) {
        float m = s[0] * (1.0f / 8388608.0f);
        out[loss_off] = fmaf(0.25f, m, m);
    }
}

extern "C" void kernel_launch(void* const* d_in, const int* in_sizes, int n_in,
                              void* d_out, int out_size) {
    const float* z   = (const float*)d_in[0];
    const float* emb = (const float*)d_in[1];
    float* out = (float*)d_out;
    cudaFuncSetAttribute(vq_kernel, cudaFuncAttributeMaxDynamicSharedMemorySize, SMEM_VQ);
    prep_kernel<<<4, 256>>>(emb);
    vq_kernel<<<NBLOCKS, THREADS, SMEM_VQ>>>(z);
    fixup_kernel<<<1024, 256>>>(z, emb);
    out_loss_kernel<<<1024, THREADS>>>(z, emb, out);
    loss_kernel<<<1, 256>>>(out, out_size - 1);
}

// round 14
// speedup vs baseline: 1.7353x; 1.3558x over previous
#include <cuda_runtime.h>
#include <cuda_fp16.h>
#include <cstdint>

#define N_ROWS   131072
#define KCODES   1024
#define DIMV     64
#define RPB      128                 // rows per vq CTA
#define NBLOCKS  (N_ROWS / RPB)      // 1024
#define THREADS  256
#define EPS_GAP  2.5e-2f
#define PRUNE_W  4e-3f
#define FT_CAND  16                  // candidate cap per row (fixup)
#define GR       32                  // flagged rows per fixup group
#define AMB_CAP  131072

// vq smem: B0 16K @0, B1 16K @16384 (both overlay the fp32 z stage used in the
// prologue: zstage [64][132] fp32 = 33792B @0), C[1024] fp32 @33792.
#define ZS_STRIDE 132
#define C_OFF     33792
#define SMEM_VQ   (33792 + 4096)

__device__ float   g_e2[KCODES];
__device__ __half  g_ehi[KCODES * DIMV];
__device__ float   g_part[1024];
__device__ int     g_idx[N_ROWS];
__device__ int     g_amb[AMB_CAP];
__device__ int     g_namb;

// ---------------- helpers ----------------
__device__ __forceinline__ void mma_f16(float* d, uint32_t a0, uint32_t a1,
                                        uint32_t a2, uint32_t a3,
                                        uint32_t b0, uint32_t b1) {
    asm volatile(
        "mma.sync.aligned.m16n8k16.row.col.f32.f16.f16.f32 "
        "{%0,%1,%2,%3}, {%4,%5,%6,%7}, {%8,%9}, {%0,%1,%2,%3};"
        : "+f"(d[0]), "+f"(d[1]), "+f"(d[2]), "+f"(d[3])
        : "r"(a0), "r"(a1), "r"(a2), "r"(a3), "r"(b0), "r"(b1));
}
__device__ __forceinline__ uint32_t smem_u32(const void* p) {
    uint32_t a;
    asm("{ .reg .u64 t; cvta.to.shared.u64 t, %1; cvt.u32.u64 %0, t; }" : "=r"(a) : "l"(p));
    return a;
}
__device__ __forceinline__ void cp16(uint32_t s, const void* g) {
    asm volatile("cp.async.cg.shared.global [%0], [%1], 16;" :: "r"(s), "l"(g));
}
__device__ __forceinline__ uint32_t pack_h2(float lo, float hi) {
    __half2 t = __floats2half2_rn(lo, hi);
    return *(uint32_t*)&t;
}

// ---------------- prep: e2 + fp16 codebook + reset ----------------
__global__ void prep_kernel(const float* __restrict__ emb) {
    if (blockIdx.x == 0 && threadIdx.x == 0) g_namb = 0;
    int k = blockIdx.x * 256 + threadIdx.x;
    if (k < KCODES) {
        float s = 0.f;
#pragma unroll
        for (int d = 0; d < DIMV; ++d) {
            float v = emb[k * DIMV + d];
            s = fmaf(v, v, s);
            g_ehi[k * DIMV + d] = __float2half_rn(v);
        }
        g_e2[k] = s;
    }
}

// merge (best,sec,idx) over disjoint code sets; ties force sec=best (-> fixup)
__device__ __forceinline__ void merge_bsi(float& b, float& s, int& i,
                                          float ob, float os, int oi) {
    if (ob < b)      { s = fminf(b, os); b = ob; i = oi; }
    else if (b < ob) { s = fminf(s, ob); }
    else             { i = min(i, oi); s = b; }
}

// ---------------- main screen: 2-pass fp16 HMMA + argmin (unchanged, R12-pass) ----------------
__global__ __launch_bounds__(THREADS, 2) void vq_kernel(const float* __restrict__ z) {
    extern __shared__ char smem[];
    const uint32_t sb = smem_u32(smem);
    const int tid  = threadIdx.x;
    const int wid  = tid >> 5;
    const int lane = tid & 31;
    const int qr   = lane >> 2;          // 0..7
    const int qc   = lane & 3;           // 0..3

    const int n0 = blockIdx.x * RPB;
    const int b  = n0 >> 12;
    const int hw = n0 & 4095;
    const int zbase = b * 262144 + hw;

    float* zsp = (float*)smem;           // [64][ZS_STRIDE], prologue only

#pragma unroll
    for (int i = 0; i < 8; ++i) {
        int idx4 = i * THREADS + tid;
        int d = idx4 >> 5, r4 = (idx4 & 31) << 2;
        float4 v = *(const float4*)(z + zbase + d * 4096 + r4);
        *(float4*)&zsp[d * ZS_STRIDE + r4] = v;
    }
    __syncthreads();

    uint32_t ah[4][4], al[4][4];
#pragma unroll
    for (int ks = 0; ks < 4; ++ks)
#pragma unroll
        for (int rg = 0; rg < 4; ++rg) {
            int r = wid * 16 + (rg & 1) * 8 + qr;
            int d = ks * 16 + (rg >> 1) * 8 + qc * 2;
            float v0 = zsp[d * ZS_STRIDE + r];
            float v1 = zsp[(d + 1) * ZS_STRIDE + r];
            float h0 = __half2float(__float2half_rn(v0));
            float h1 = __half2float(__float2half_rn(v1));
            ah[ks][rg] = pack_h2(h0, h1);
            al[ks][rg] = pack_h2(v0 - h0, v1 - h1);
        }
    __syncthreads();   // zstage dead; B bufs overwrite it

    float* csm = (float*)(smem + C_OFF);
#pragma unroll
    for (int i = 0; i < 4; ++i) csm[i * 256 + tid] = g_e2[i * 256 + tid];

    auto issue_chunk = [&](int c, int bi) {
        uint32_t bbuf = sb + bi * 16384;
#pragma unroll
        for (int i = 0; i < 4; ++i) {
            int idx = i * THREADS + tid;
            int cr = idx >> 3, u = idx & 7;
            uint32_t doff = cr * 128 + ((u ^ (cr & 7)) << 4);
            cp16(bbuf + doff, (const char*)g_ehi + c * 16384 + idx * 16);
        }
        asm volatile("cp.async.commit_group;" ::: "memory");
    };

    issue_chunk(0, 0);
    issue_chunk(1, 1);

    float best[2], sec[2];
    int   bidx[2];
#pragma unroll
    for (int g = 0; g < 2; ++g) { best[g] = 3.4028235e38f; sec[g] = 3.4028235e38f; bidx[g] = 0; }

    for (int c = 0; c < 8; ++c) {
        if (c < 7) asm volatile("cp.async.wait_group 1;" ::: "memory");
        else       asm volatile("cp.async.wait_group 0;" ::: "memory");
        __syncthreads();

        const char* bb = smem + (c & 1) * 16384;
        const int cbase = c * 128;
#pragma unroll
        for (int s = 0; s < 2; ++s) {
            float acc[8][4];
#pragma unroll
            for (int a = 0; a < 8; ++a)
#pragma unroll
                for (int q = 0; q < 4; ++q) acc[a][q] = 0.f;

#pragma unroll
            for (int ks = 0; ks < 4; ++ks) {
#pragma unroll
                for (int a = 0; a < 8; ++a) {
                    uint32_t rowoff = (uint32_t)(s * 64 + a * 8 + qr) * 128 + qc * 4;
                    uint32_t u0 = (uint32_t)(((ks * 2)     ^ qr) << 4);
                    uint32_t u1 = (uint32_t)(((ks * 2 + 1) ^ qr) << 4);
                    uint32_t b0 = *(const uint32_t*)(bb + rowoff + u0);
                    uint32_t b1 = *(const uint32_t*)(bb + rowoff + u1);
                    mma_f16(acc[a], ah[ks][0], ah[ks][1], ah[ks][2], ah[ks][3], b0, b1);
                    mma_f16(acc[a], al[ks][0], al[ks][1], al[ks][2], al[ks][3], b0, b1);
                }
            }
#pragma unroll
            for (int a = 0; a < 8; ++a) {
                int k0 = cbase + s * 64 + a * 8 + qc * 2;
                float2 cv = *(const float2*)(smem + C_OFF + k0 * 4);
                float s00 = fmaf(-2.f, acc[a][0], cv.x);
                float s01 = fmaf(-2.f, acc[a][1], cv.y);
                float s10 = fmaf(-2.f, acc[a][2], cv.x);
                float s11 = fmaf(-2.f, acc[a][3], cv.y);
                if (s00 < best[0]) { sec[0] = best[0]; best[0] = s00; bidx[0] = k0; } else if (s00 < sec[0]) sec[0] = s00;
                if (s01 < best[0]) { sec[0] = best[0]; best[0] = s01; bidx[0] = k0 + 1; } else if (s01 < sec[0]) sec[0] = s01;
                if (s10 < best[1]) { sec[1] = best[1]; best[1] = s10; bidx[1] = k0; } else if (s10 < sec[1]) sec[1] = s10;
                if (s11 < best[1]) { sec[1] = best[1]; best[1] = s11; bidx[1] = k0 + 1; } else if (s11 < sec[1]) sec[1] = s11;
            }
        }
        __syncthreads();
        if (c + 2 < 8) issue_chunk(c + 2, c & 1);
    }

#pragma unroll
    for (int off = 1; off <= 2; off <<= 1) {
#pragma unroll
        for (int g = 0; g < 2; ++g) {
            float ob = __shfl_xor_sync(0xffffffffu, best[g], off);
            float os = __shfl_xor_sync(0xffffffffu, sec[g],  off);
            int   oi = __shfl_xor_sync(0xffffffffu, bidx[g], off);
            merge_bsi(best[g], sec[g], bidx[g], ob, os, oi);
        }
    }
    if (qc == 0) {
#pragma unroll
        for (int g = 0; g < 2; ++g) {
            int n = n0 + wid * 16 + g * 8 + qr;
            g_idx[n] = bidx[g];
            if (sec[g] - best[g] < EPS_GAP) {
                int slot = atomicAdd(&g_namb, 1);
                if (slot < AMB_CAP) g_amb[slot] = n;
            }
        }
    }
}

// ---------------- batched fixup: 32 rows/CTA, codebook streamed via smem ----------------
// Pass A: dot-form fp32 distances -> row min. Pass B: collect candidates in
// (min + PRUNE_W) window. fp64 diff-form on candidates -> lex-(value,k) argmin.
__global__ __launch_bounds__(256) void fixup_kernel(
    const float* __restrict__ z, const float* __restrict__ emb)
{
    __shared__ float es[128 * 68];        // tile: 128 codes x 64 d (stride 68)
    __shared__ float zs[GR * 68];         // 32 rows x 64 d
    __shared__ float e2t[128];
    __shared__ int   rown[GR];
    __shared__ int   cnt[GR];
    __shared__ int   cand[GR * FT_CAND];

    const int tid = threadIdx.x;
    const int r   = tid >> 3;             // row within group, 0..31
    const int sub = tid & 7;              // 8 threads per row

    int namb = min(g_namb, AMB_CAP);
    int ngroups = (namb + GR - 1) / GR;

    for (int grp = blockIdx.x; grp < ngroups; grp += gridDim.x) {
        int base  = grp * GR;
        int nrows = min(GR, namb - base);
        if (tid < GR) {
            rown[tid] = g_amb[base + (tid < nrows ? tid : 0)];
            cnt[tid]  = 0;
        }
        __syncthreads();

        // load the 32 z rows into smem
#pragma unroll
        for (int i = 0; i < 8; ++i) {
            int idx = i * 256 + tid;
            int rr = idx >> 6, d = idx & 63;
            int n = rown[rr];
            zs[rr * 68 + d] = z[(n >> 12) * 262144 + d * 4096 + (n & 4095)];
        }
        __syncthreads();

        // cache own row in regs; z^2 (fixed sequential order)
        float4 zf[16];
        float z2 = 0.f;
#pragma unroll
        for (int i = 0; i < 16; ++i) {
            zf[i] = *(const float4*)&zs[r * 68 + i * 4];
            z2 = fmaf(zf[i].x, zf[i].x, z2);
            z2 = fmaf(zf[i].y, zf[i].y, z2);
            z2 = fmaf(zf[i].z, zf[i].z, z2);
            z2 = fmaf(zf[i].w, zf[i].w, z2);
        }

        // ---- pass A: fp32 min over all 1024 codes ----
        float lmin = 3.4028235e38f;
        for (int t = 0; t < 8; ++t) {
#pragma unroll
            for (int i = 0; i < 8; ++i) {
                int idx4 = i * 256 + tid;
                int code = idx4 >> 4, d4 = idx4 & 15;
                float4 v = *(const float4*)(emb + (t * 128 + code) * 64 + d4 * 4);
                *(float4*)&es[code * 68 + d4 * 4] = v;
            }
            if (tid < 128) e2t[tid] = g_e2[t * 128 + tid];
            __syncthreads();
#pragma unroll
            for (int j = 0; j < 16; ++j) {
                int c = j * 8 + sub;
                const float4* ef = (const float4*)&es[c * 68];
                float acc = 0.f;
#pragma unroll
                for (int i = 0; i < 16; ++i) {
                    float4 e = ef[i];
                    acc = fmaf(zf[i].x, e.x, acc);
                    acc = fmaf(zf[i].y, e.y, acc);
                    acc = fmaf(zf[i].z, e.z, acc);
                    acc = fmaf(zf[i].w, e.w, acc);
                }
                float d = fmaf(-2.f, acc, z2 + e2t[c]);
                lmin = fminf(lmin, d);
            }
            __syncthreads();
        }
#pragma unroll
        for (int o = 1; o < 8; o <<= 1)
            lmin = fminf(lmin, __shfl_xor_sync(0xffffffffu, lmin, o));

        // ---- pass B: collect candidates within window ----
        for (int t = 0; t < 8; ++t) {
#pragma unroll
            for (int i = 0; i < 8; ++i) {
                int idx4 = i * 256 + tid;
                int code = idx4 >> 4, d4 = idx4 & 15;
                float4 v = *(const float4*)(emb + (t * 128 + code) * 64 + d4 * 4);
                *(float4*)&es[code * 68 + d4 * 4] = v;
            }
            if (tid < 128) e2t[tid] = g_e2[t * 128 + tid];
            __syncthreads();
#pragma unroll
            for (int j = 0; j < 16; ++j) {
                int c = j * 8 + sub;
                const float4* ef = (const float4*)&es[c * 68];
                float acc = 0.f;
#pragma unroll
                for (int i = 0; i < 16; ++i) {
                    float4 e = ef[i];
                    acc = fmaf(zf[i].x, e.x, acc);
                    acc = fmaf(zf[i].y, e.y, acc);
                    acc = fmaf(zf[i].z, e.z, acc);
                    acc = fmaf(zf[i].w, e.w, acc);
                }
                float d = fmaf(-2.f, acc, z2 + e2t[c]);
                if (d < lmin + PRUNE_W) {
                    int slot = atomicAdd(&cnt[r], 1);
                    if (slot < FT_CAND) cand[r * FT_CAND + slot] = t * 128 + c;
                }
            }
            __syncthreads();
        }

        // ---- fp64 exact decision over candidates ----
        int nc = min(cnt[r], FT_CAND);
        double bv = 1e300; int bk = 0x7fffffff;
        for (int q = sub; q < nc; q += 8) {
            int k = cand[r * FT_CAND + q];
            const float* e = emb + k * DIMV;
            double s = 0.0;
#pragma unroll
            for (int i = 0; i < 16; ++i) {
                double d0 = (double)zf[i].x - (double)e[i * 4 + 0]; s = fma(d0, d0, s);
                double d1 = (double)zf[i].y - (double)e[i * 4 + 1]; s = fma(d1, d1, s);
                double d2 = (double)zf[i].z - (double)e[i * 4 + 2]; s = fma(d2, d2, s);
                double d3 = (double)zf[i].w - (double)e[i * 4 + 3]; s = fma(d3, d3, s);
            }
            if (s < bv || (s == bv && k < bk)) { bv = s; bk = k; }
        }
#pragma unroll
        for (int o = 1; o < 8; o <<= 1) {
            double ov = __shfl_xor_sync(0xffffffffu, bv, o);
            int    ok = __shfl_xor_sync(0xffffffffu, bk, o);
            if (ov < bv || (ov == bv && ok < bk)) { bv = ov; bk = ok; }
        }
        if (sub == 0 && r < nrows) g_idx[rown[r]] = bk;
        __syncthreads();
    }
}

// ---------------- gather + output + loss partials ----------------
__global__ __launch_bounds__(THREADS) void out_loss_kernel(
    const float* __restrict__ z, const float* __restrict__ emb,
    float* __restrict__ out)
{
    __shared__ int   ks[128];
    __shared__ float qs[128 * 65];
    __shared__ float wsum[8];
    const int tid = threadIdx.x;
    const int wid = tid >> 5, lane = tid & 31;
    const int n0 = blockIdx.x * 128;
    const int b  = n0 >> 12;
    const int hw = n0 & 4095;
    const int zbase = b * 262144 + hw;

    if (tid < 128) ks[tid] = g_idx[n0 + tid];
    __syncthreads();
    for (int rr = wid; rr < 128; rr += 8) {
        float2 e2v = ((const float2*)(emb + ks[rr] * DIMV))[lane];
        qs[rr * 65 + lane * 2]     = e2v.x;
        qs[rr * 65 + lane * 2 + 1] = e2v.y;
    }
    __syncthreads();

    float lsum = 0.f;
#pragma unroll
    for (int i = 0; i < 32; ++i) {
        int idx = i * THREADS + tid;
        int d = idx >> 7, r = idx & 127;
        float q = qs[r * 65 + d];
        int g = zbase + d * 4096 + r;
        out[g] = q;
        float diff = q - __ldg(&z[g]);
        lsum = fmaf(diff, diff, lsum);
    }
#pragma unroll
    for (int o = 16; o > 0; o >>= 1)
        lsum += __shfl_down_sync(0xffffffffu, lsum, o);
    if ((tid & 31) == 0) wsum[tid >> 5] = lsum;
    __syncthreads();
    if (tid == 0) {
        float s = 0.f;
#pragma unroll
        for (int w = 0; w < 8; ++w) s += wsum[w];
        g_part[blockIdx.x] = s;
    }
}

__global__ void loss_kernel(float* __restrict__ out, int loss_off) {
    __shared__ float s[256];
    int t = threadIdx.x;
    s[t] = g_part[t] + g_part[t + 256] + g_part[t + 512] + g_part[t + 768];
    __syncthreads();
    for (int o = 128; o > 0; o >>= 1) {
        if (t < o) s[t] += s[t + o];
        __syncthreads();
    }
    if (t == 0) {
        float m = s[0] * (1.0f / 8388608.0f);
        out[loss_off] = fmaf(0.25f, m, m);
    }
}

extern "C" void kernel_launch(void* const* d_in, const int* in_sizes, int n_in,
                              void* d_out, int out_size) {
    const float* z   = (const float*)d_in[0];
    const float* emb = (const float*)d_in[1];
    float* out = (float*)d_out;
    cudaFuncSetAttribute(vq_kernel, cudaFuncAttributeMaxDynamicSharedMemorySize, SMEM_VQ);
    prep_kernel<<<4, 256>>>(emb);
    vq_kernel<<<NBLOCKS, THREADS, SMEM_VQ>>>(z);
    fixup_kernel<<<256, 256>>>(z, emb);
    out_loss_kernel<<<1024, THREADS>>>(z, emb, out);
    loss_kernel<<<1, 256>>>(out, out_size - 1);
}